// round 1
// baseline (speedup 1.0000x reference)
#include <cuda_runtime.h>
#include <cuda_bf16.h>

// Problem constants (fixed by the dataset)
#define NN      50000
#define IN_C    128
#define HID     64
#define HEADS   4
#define OUT_C   16
#define EE      600000
#define ET      650000          // edges + self loops
#define F1      (HEADS*HID)     // 256
#define NEG_SLOPE 0.2f

// ---------------- scratch (static device globals; no allocation) ----------------
__device__ __align__(16) float    g_h1[NN*F1];     // x @ W1            [N,256]
__device__ __align__(16) float    g_out1[NN*F1];   // layer1 aggregated [N,256]
__device__ __align__(16) float    g_h2[NN*OUT_C];  // relu(out1) @ W2   [N,16]
__device__ float    g_asrc1[NN*HEADS], g_adst1[NN*HEADS];
__device__ unsigned g_m1[NN*HEADS];
__device__ float    g_den1[NN*HEADS];
__device__ float    g_asrc2[NN], g_adst2[NN];
__device__ unsigned g_m2[NN];
__device__ float    g_den2[NN];

// ---------------- helpers ----------------
__device__ __forceinline__ unsigned enc_f(float f) {
    unsigned u = __float_as_uint(f);
    return (u & 0x80000000u) ? ~u : (u | 0x80000000u);
}
__device__ __forceinline__ float dec_f(unsigned u) {
    return (u & 0x80000000u) ? __uint_as_float(u & 0x7FFFFFFFu) : __uint_as_float(~u);
}
__device__ __forceinline__ float leaky(float v) {
    return fmaxf(v, 0.f) + NEG_SLOPE * fminf(v, 0.f);
}
__device__ __forceinline__ void edge_sd(const int* __restrict__ ei, int eid, int& s, int& d) {
    if (eid < EE) { s = ei[eid]; d = ei[EE + eid]; }
    else          { s = d = eid - EE; }
}
__device__ __forceinline__ void red4(float* p, float a, float b, float c, float d) {
    asm volatile("red.global.add.v4.f32 [%0], {%1,%2,%3,%4};"
                 :: "l"(p), "f"(a), "f"(b), "f"(c), "f"(d) : "memory");
}

// ---------------- init kernels ----------------
__global__ void init_stats_kernel() {
    int t = blockIdx.x * blockDim.x + threadIdx.x;
    if (t < NN*HEADS) { g_m1[t] = 0u; g_den1[t] = 0.f; }
    if (t < NN)       { g_m2[t] = 0u; g_den2[t] = 0.f; }
}
__global__ void init_out1_kernel(const float* __restrict__ b1) {
    int t = blockIdx.x * blockDim.x + threadIdx.x;
    if (t < NN*F1) g_out1[t] = b1[t & (F1-1)];
}
__global__ void init_out_kernel(float* __restrict__ out, const float* __restrict__ b2) {
    int t = blockIdx.x * blockDim.x + threadIdx.x;
    if (t < NN*OUT_C) out[t] = b2[t & (OUT_C-1)];
}

// ---------------- GEMM1: h1 = x @ W1  (M=50000, K=128, N=256) ----------------
#define BM 64
#define BN 64
#define BK 64
__global__ void gemm1_kernel(const float* __restrict__ x, const float* __restrict__ W) {
    __shared__ float xs[BM][BK + 1];
    __shared__ float ws[BK][BN + 1];
    int tid  = threadIdx.x;
    int row0 = blockIdx.y * BM;
    int col0 = blockIdx.x * BN;
    float acc[4][4] = {};
    int ty = tid >> 4, tx = tid & 15;

    for (int k0 = 0; k0 < IN_C; k0 += BK) {
        // load x tile [BM][BK] (float4 along K)
        for (int i = tid; i < BM * (BK/4); i += 256) {
            int r = i / (BK/4), c = (i % (BK/4)) * 4;
            float4 v = make_float4(0.f,0.f,0.f,0.f);
            int gr = row0 + r;
            if (gr < NN) v = *reinterpret_cast<const float4*>(&x[gr * IN_C + k0 + c]);
            xs[r][c] = v.x; xs[r][c+1] = v.y; xs[r][c+2] = v.z; xs[r][c+3] = v.w;
        }
        // load W tile [BK][BN]
        for (int i = tid; i < BK * (BN/4); i += 256) {
            int r = i / (BN/4), c = (i % (BN/4)) * 4;
            float4 v = *reinterpret_cast<const float4*>(&W[(k0 + r) * F1 + col0 + c]);
            ws[r][c] = v.x; ws[r][c+1] = v.y; ws[r][c+2] = v.z; ws[r][c+3] = v.w;
        }
        __syncthreads();
        #pragma unroll 8
        for (int k = 0; k < BK; k++) {
            float a[4], b[4];
            #pragma unroll
            for (int i = 0; i < 4; i++) a[i] = xs[ty*4 + i][k];
            #pragma unroll
            for (int j = 0; j < 4; j++) b[j] = ws[k][tx*4 + j];
            #pragma unroll
            for (int i = 0; i < 4; i++)
                #pragma unroll
                for (int j = 0; j < 4; j++)
                    acc[i][j] = fmaf(a[i], b[j], acc[i][j]);
        }
        __syncthreads();
    }
    #pragma unroll
    for (int i = 0; i < 4; i++) {
        int gr = row0 + ty*4 + i;
        if (gr < NN) {
            #pragma unroll
            for (int j = 0; j < 4; j++)
                g_h1[gr * F1 + col0 + tx*4 + j] = acc[i][j];
        }
    }
}

// ---------------- attention logits layer 1: a_src/a_dst [N,4] ----------------
__global__ void attn1_kernel(const float* __restrict__ att_src, const float* __restrict__ att_dst) {
    int gw   = (blockIdx.x * blockDim.x + threadIdx.x) >> 5;
    int lane = threadIdx.x & 31;
    if (gw >= NN*HEADS) return;
    int n = gw >> 2, hh = gw & 3;
    const float* hp = &g_h1[n * F1 + hh * HID];
    float s = 0.f, d = 0.f;
    #pragma unroll
    for (int c = lane; c < HID; c += 32) {
        float v = hp[c];
        s += v * att_src[hh * HID + c];
        d += v * att_dst[hh * HID + c];
    }
    #pragma unroll
    for (int o = 16; o; o >>= 1) {
        s += __shfl_xor_sync(0xFFFFFFFFu, s, o);
        d += __shfl_xor_sync(0xFFFFFFFFu, d, o);
    }
    if (lane == 0) { g_asrc1[gw] = s; g_adst1[gw] = d; }
}

// ---------------- edge softmax stats layer 1 ----------------
__global__ void edge_max1_kernel(const int* __restrict__ ei) {
    int t = blockIdx.x * blockDim.x + threadIdx.x;
    if (t >= ET*HEADS) return;
    int eid = t >> 2, hh = t & 3;
    int s, d; edge_sd(ei, eid, s, d);
    float v = leaky(g_asrc1[s*HEADS + hh] + g_adst1[d*HEADS + hh]);
    atomicMax(&g_m1[d*HEADS + hh], enc_f(v));
}
__global__ void edge_den1_kernel(const int* __restrict__ ei) {
    int t = blockIdx.x * blockDim.x + threadIdx.x;
    if (t >= ET*HEADS) return;
    int eid = t >> 2, hh = t & 3;
    int s, d; edge_sd(ei, eid, s, d);
    float v = leaky(g_asrc1[s*HEADS + hh] + g_adst1[d*HEADS + hh]);
    float ex = __expf(v - dec_f(g_m1[d*HEADS + hh]));
    atomicAdd(&g_den1[d*HEADS + hh], ex);
}

// ---------------- aggregation layer 1: out1[dst] += alpha * h1[src] ----------------
// one warp per edge; lane l handles components [8l, 8l+8) (head = l/8)
__global__ void agg1_kernel(const int* __restrict__ ei) {
    int gw   = (blockIdx.x * blockDim.x + threadIdx.x) >> 5;
    int lane = threadIdx.x & 31;
    if (gw >= ET) return;
    int s, d; edge_sd(ei, gw, s, d);
    float alpha = 0.f;
    if (lane < HEADS) {
        float v = leaky(g_asrc1[s*HEADS + lane] + g_adst1[d*HEADS + lane]);
        alpha = __expf(v - dec_f(g_m1[d*HEADS + lane])) / g_den1[d*HEADS + lane];
    }
    float am = __shfl_sync(0xFFFFFFFFu, alpha, lane >> 3);
    const float4* hp = reinterpret_cast<const float4*>(&g_h1[s * F1 + lane * 8]);
    float4 v0 = hp[0], v1 = hp[1];
    float* op = &g_out1[d * F1 + lane * 8];
    red4(op,     am*v0.x, am*v0.y, am*v0.z, am*v0.w);
    red4(op + 4, am*v1.x, am*v1.y, am*v1.z, am*v1.w);
}

// ---------------- GEMM2 (+ relu on read, + attention logits layer 2) ----------------
// one warp per node; W2 [256,16] staged in smem (padded rows of 17)
__global__ void gemm2_kernel(const float* __restrict__ W2,
                             const float* __restrict__ att_src2,
                             const float* __restrict__ att_dst2) {
    __shared__ float w2s[F1 * 17];
    __shared__ float as2[OUT_C], ad2[OUT_C];
    int tid = threadIdx.x;
    for (int i = tid; i < F1 * OUT_C; i += 256) {
        int k = i >> 4, j = i & 15;
        w2s[k * 17 + j] = W2[i];
    }
    if (tid < OUT_C) { as2[tid] = att_src2[tid]; ad2[tid] = att_dst2[tid]; }
    __syncthreads();

    int gw   = (blockIdx.x * blockDim.x + tid) >> 5;
    int lane = tid & 31;
    if (gw >= NN) return;
    float acc[OUT_C] = {};
    const float* row = &g_out1[gw * F1];
    #pragma unroll
    for (int i = 0; i < 8; i++) {
        float v = fmaxf(row[lane + 32 * i], 0.f);
        const float* wr = &w2s[(lane + 32 * i) * 17];
        #pragma unroll
        for (int j = 0; j < OUT_C; j++) acc[j] = fmaf(v, wr[j], acc[j]);
    }
    #pragma unroll
    for (int j = 0; j < OUT_C; j++)
        #pragma unroll
        for (int o = 16; o; o >>= 1)
            acc[j] += __shfl_xor_sync(0xFFFFFFFFu, acc[j], o);
    if (lane == 0) {
        float s = 0.f, dd = 0.f;
        #pragma unroll
        for (int j = 0; j < OUT_C; j++) {
            g_h2[gw * OUT_C + j] = acc[j];
            s  += acc[j] * as2[j];
            dd += acc[j] * ad2[j];
        }
        g_asrc2[gw] = s; g_adst2[gw] = dd;
    }
}

// ---------------- edge softmax stats layer 2 (H=1) ----------------
__global__ void edge_max2_kernel(const int* __restrict__ ei) {
    int eid = blockIdx.x * blockDim.x + threadIdx.x;
    if (eid >= ET) return;
    int s, d; edge_sd(ei, eid, s, d);
    float v = leaky(g_asrc2[s] + g_adst2[d]);
    atomicMax(&g_m2[d], enc_f(v));
}
__global__ void edge_den2_kernel(const int* __restrict__ ei) {
    int eid = blockIdx.x * blockDim.x + threadIdx.x;
    if (eid >= ET) return;
    int s, d; edge_sd(ei, eid, s, d);
    float v = leaky(g_asrc2[s] + g_adst2[d]);
    atomicAdd(&g_den2[d], __expf(v - dec_f(g_m2[d])));
}

// ---------------- aggregation layer 2: out[dst] += alpha * h2[src] ----------------
// 4 threads per edge; each does one float4
__global__ void agg2_kernel(const int* __restrict__ ei, float* __restrict__ out) {
    int t = blockIdx.x * blockDim.x + threadIdx.x;
    if (t >= ET * 4) return;
    int eid = t >> 2, q = t & 3;
    int s, d; edge_sd(ei, eid, s, d);
    float v = leaky(g_asrc2[s] + g_adst2[d]);
    float alpha = __expf(v - dec_f(g_m2[d])) / g_den2[d];
    float4 hv = *reinterpret_cast<const float4*>(&g_h2[s * OUT_C + q * 4]);
    red4(&out[d * OUT_C + q * 4], alpha*hv.x, alpha*hv.y, alpha*hv.z, alpha*hv.w);
}

// ---------------- launch ----------------
extern "C" void kernel_launch(void* const* d_in, const int* in_sizes, int n_in,
                              void* d_out, int out_size) {
    const float* x    = (const float*)d_in[0];
    const int*   ei   = (const int*)  d_in[1];
    const float* W1   = (const float*)d_in[2];
    const float* as1  = (const float*)d_in[3];
    const float* ad1  = (const float*)d_in[4];
    const float* b1   = (const float*)d_in[5];
    const float* W2   = (const float*)d_in[6];
    const float* as2  = (const float*)d_in[7];
    const float* ad2  = (const float*)d_in[8];
    const float* b2   = (const float*)d_in[9];
    float* out = (float*)d_out;

    // init
    init_stats_kernel<<<(NN*HEADS + 255) / 256, 256>>>();
    init_out1_kernel<<<(NN*F1 + 255) / 256, 256>>>(b1);
    init_out_kernel<<<(NN*OUT_C + 255) / 256, 256>>>(out, b2);

    // layer 1
    gemm1_kernel<<<dim3(F1 / BN, (NN + BM - 1) / BM), 256>>>(x, W1);
    attn1_kernel<<<(NN*HEADS*32 + 255) / 256, 256>>>(as1, ad1);
    edge_max1_kernel<<<(ET*HEADS + 255) / 256, 256>>>(ei);
    edge_den1_kernel<<<(ET*HEADS + 255) / 256, 256>>>(ei);
    agg1_kernel<<<(ET*32 + 255) / 256, 256>>>(ei);

    // layer 2
    gemm2_kernel<<<(NN*32 + 255) / 256, 256>>>(W2, as2, ad2);
    edge_max2_kernel<<<(ET + 255) / 256, 256>>>(ei);
    edge_den2_kernel<<<(ET + 255) / 256, 256>>>(ei);
    agg2_kernel<<<(ET*4 + 255) / 256, 256>>>(ei, out);
}

// round 2
// speedup vs baseline: 1.4476x; 1.4476x over previous
#include <cuda_runtime.h>
#include <cuda_bf16.h>

// Problem constants (fixed by the dataset)
#define NN      50000
#define IN_C    128
#define HID     64
#define HEADS   4
#define OUT_C   16
#define EE      600000
#define ET      650000          // edges + self loops
#define F1      (HEADS*HID)     // 256
#define NEG_SLOPE 0.2f

// ---------------- scratch (static device globals; no allocation) ----------------
__device__ __align__(16) float g_h1[NN*F1];     // x @ W1            [N,256]
__device__ __align__(16) float g_out1[NN*F1];   // layer1 aggregated [N,256]
__device__ __align__(16) float g_h2[NN*OUT_C];  // relu(out1) @ W2   [N,16]
__device__ __align__(16) float g_asrc1[NN*HEADS];
__device__ __align__(16) float g_adst1[NN*HEADS];
__device__ float g_asrc2[NN], g_adst2[NN];
// CSR (grouped by dst)
__device__ int g_deg[NN];
__device__ int g_pos[NN];
__device__ int g_off[NN+1];
__device__ int g_srcs[ET];

// ---------------- helpers ----------------
__device__ __forceinline__ float leaky(float v) {
    return fmaxf(v, 0.f) + NEG_SLOPE * fminf(v, 0.f);
}
__device__ __forceinline__ void edge_sd(const int* __restrict__ ei, int eid, int& s, int& d) {
    if (eid < EE) { s = ei[eid]; d = ei[EE + eid]; }
    else          { s = d = eid - EE; }
}

// ---------------- CSR build ----------------
__global__ void csr_init_kernel() {
    int t = blockIdx.x * blockDim.x + threadIdx.x;
    if (t < NN) { g_deg[t] = 0; g_pos[t] = 0; }
}
__global__ void csr_hist_kernel(const int* __restrict__ ei) {
    int eid = blockIdx.x * blockDim.x + threadIdx.x;
    if (eid >= ET) return;
    int s, d; edge_sd(ei, eid, s, d);
    atomicAdd(&g_deg[d], 1);
}
__global__ void csr_scan_kernel() {   // single block, 1024 threads
    __shared__ int sh[1024];
    int t = threadIdx.x;
    const int CH = (NN + 1023) / 1024;
    int base = t * CH;
    int s = 0;
    for (int i = 0; i < CH; i++) { int id = base + i; if (id < NN) s += g_deg[id]; }
    sh[t] = s;
    __syncthreads();
    for (int off = 1; off < 1024; off <<= 1) {
        int v = (t >= off) ? sh[t - off] : 0;
        __syncthreads();
        sh[t] += v;
        __syncthreads();
    }
    int run = sh[t] - s;   // exclusive prefix
    for (int i = 0; i < CH; i++) {
        int id = base + i;
        if (id < NN) { g_off[id] = run; run += g_deg[id]; }
    }
    if (t == 1023) g_off[NN] = sh[1023];
}
__global__ void csr_scatter_kernel(const int* __restrict__ ei) {
    int eid = blockIdx.x * blockDim.x + threadIdx.x;
    if (eid >= ET) return;
    int s, d; edge_sd(ei, eid, s, d);
    int p = atomicAdd(&g_pos[d], 1);
    g_srcs[g_off[d] + p] = s;
}

// ---------------- GEMM1: h1 = x @ W1  (M=50000, K=128, N=256) ----------------
// 128x128 block tile, 8x8 per thread, BK=16
#define BM 128
#define BN 128
#define BK 16
__global__ void gemm1_kernel(const float* __restrict__ x, const float* __restrict__ W) {
    __shared__ float xs[BK][BM + 4];
    __shared__ float ws[BK][BN + 4];
    int tid  = threadIdx.x;
    int row0 = blockIdx.y * BM;
    int col0 = blockIdx.x * BN;
    int ty = tid >> 4, tx = tid & 15;
    float acc[8][8] = {};

    for (int k0 = 0; k0 < IN_C; k0 += BK) {
        // x tile [BM][BK] -> transposed into xs[k][m]
        #pragma unroll
        for (int i = tid; i < BM * (BK/4); i += 256) {
            int r = i / (BK/4), c = (i % (BK/4)) * 4;
            int gr = row0 + r;
            float4 v = make_float4(0.f,0.f,0.f,0.f);
            if (gr < NN) v = *reinterpret_cast<const float4*>(&x[gr * IN_C + k0 + c]);
            xs[c][r] = v.x; xs[c+1][r] = v.y; xs[c+2][r] = v.z; xs[c+3][r] = v.w;
        }
        // W tile [BK][BN]
        #pragma unroll
        for (int i = tid; i < BK * (BN/4); i += 256) {
            int r = i / (BN/4), c = (i % (BN/4)) * 4;
            float4 v = *reinterpret_cast<const float4*>(&W[(k0 + r) * F1 + col0 + c]);
            ws[r][c] = v.x; ws[r][c+1] = v.y; ws[r][c+2] = v.z; ws[r][c+3] = v.w;
        }
        __syncthreads();
        #pragma unroll
        for (int k = 0; k < BK; k++) {
            float a[8], b[8];
            #pragma unroll
            for (int i = 0; i < 8; i++) a[i] = xs[k][ty*8 + i];
            #pragma unroll
            for (int j = 0; j < 8; j++) b[j] = ws[k][tx*8 + j];
            #pragma unroll
            for (int i = 0; i < 8; i++)
                #pragma unroll
                for (int j = 0; j < 8; j++)
                    acc[i][j] = fmaf(a[i], b[j], acc[i][j]);
        }
        __syncthreads();
    }
    #pragma unroll
    for (int i = 0; i < 8; i++) {
        int gr = row0 + ty*8 + i;
        if (gr < NN) {
            float4* op = reinterpret_cast<float4*>(&g_h1[gr * F1 + col0 + tx*8]);
            op[0] = make_float4(acc[i][0], acc[i][1], acc[i][2], acc[i][3]);
            op[1] = make_float4(acc[i][4], acc[i][5], acc[i][6], acc[i][7]);
        }
    }
}

// ---------------- attention logits layer 1: a_src/a_dst [N,4] ----------------
__global__ void attn1_kernel(const float* __restrict__ att_src, const float* __restrict__ att_dst) {
    int gw   = (blockIdx.x * blockDim.x + threadIdx.x) >> 5;
    int lane = threadIdx.x & 31;
    if (gw >= NN*HEADS) return;
    int n = gw >> 2, hh = gw & 3;
    const float* hp = &g_h1[n * F1 + hh * HID];
    float s = 0.f, d = 0.f;
    #pragma unroll
    for (int c = lane; c < HID; c += 32) {
        float v = hp[c];
        s += v * att_src[hh * HID + c];
        d += v * att_dst[hh * HID + c];
    }
    #pragma unroll
    for (int o = 16; o; o >>= 1) {
        s += __shfl_xor_sync(0xFFFFFFFFu, s, o);
        d += __shfl_xor_sync(0xFFFFFFFFu, d, o);
    }
    if (lane == 0) { g_asrc1[gw] = s; g_adst1[gw] = d; }
}

// ---------------- fused layer-1 softmax + aggregation (one warp per dst node) ----------------
__global__ void agg1_kernel(const float* __restrict__ b1) {
    int gw   = (blockIdx.x * blockDim.x + threadIdx.x) >> 5;
    int lane = threadIdx.x & 31;
    if (gw >= NN) return;
    int n = gw;
    int beg = g_off[n], end = g_off[n+1];
    float4 ad4 = *reinterpret_cast<const float4*>(&g_adst1[n * HEADS]);

    // pass 1: per-head max over incoming edges (lane-strided)
    float m0 = -1e30f, m1 = -1e30f, m2 = -1e30f, m3 = -1e30f;
    for (int e = beg + lane; e < end; e += 32) {
        int s = g_srcs[e];
        float4 as4 = *reinterpret_cast<const float4*>(&g_asrc1[s * HEADS]);
        m0 = fmaxf(m0, leaky(as4.x + ad4.x));
        m1 = fmaxf(m1, leaky(as4.y + ad4.y));
        m2 = fmaxf(m2, leaky(as4.z + ad4.z));
        m3 = fmaxf(m3, leaky(as4.w + ad4.w));
    }
    #pragma unroll
    for (int o = 16; o; o >>= 1) {
        m0 = fmaxf(m0, __shfl_xor_sync(0xFFFFFFFFu, m0, o));
        m1 = fmaxf(m1, __shfl_xor_sync(0xFFFFFFFFu, m1, o));
        m2 = fmaxf(m2, __shfl_xor_sync(0xFFFFFFFFu, m2, o));
        m3 = fmaxf(m3, __shfl_xor_sync(0xFFFFFFFFu, m3, o));
    }

    // lane's head and its max / adst
    int hh = lane >> 3;                               // 0..3, lane handles cols [lane*8, lane*8+8)
    float mh = (hh == 0) ? m0 : (hh == 1) ? m1 : (hh == 2) ? m2 : m3;
    float adh = (hh == 0) ? ad4.x : (hh == 1) ? ad4.y : (hh == 2) ? ad4.z : ad4.w;

    // pass 2: serial over edges, accumulate ex * h1[src] and den in registers
    float den = 0.f;
    float acc[8] = {};
    for (int e = beg; e < end; e++) {
        int s = g_srcs[e];                            // uniform across warp -> broadcast
        float as = g_asrc1[s * HEADS + hh];
        float ex = __expf(leaky(as + adh) - mh);
        den += ex;
        const float4* hp = reinterpret_cast<const float4*>(&g_h1[s * F1 + lane * 8]);
        float4 v0 = hp[0], v1 = hp[1];
        acc[0] = fmaf(ex, v0.x, acc[0]); acc[1] = fmaf(ex, v0.y, acc[1]);
        acc[2] = fmaf(ex, v0.z, acc[2]); acc[3] = fmaf(ex, v0.w, acc[3]);
        acc[4] = fmaf(ex, v1.x, acc[4]); acc[5] = fmaf(ex, v1.y, acc[5]);
        acc[6] = fmaf(ex, v1.z, acc[6]); acc[7] = fmaf(ex, v1.w, acc[7]);
    }
    float inv = 1.f / den;
    float4 b0 = *reinterpret_cast<const float4*>(&b1[lane * 8]);
    float4 b4 = *reinterpret_cast<const float4*>(&b1[lane * 8 + 4]);
    float4* op = reinterpret_cast<float4*>(&g_out1[n * F1 + lane * 8]);
    op[0] = make_float4(acc[0]*inv + b0.x, acc[1]*inv + b0.y, acc[2]*inv + b0.z, acc[3]*inv + b0.w);
    op[1] = make_float4(acc[4]*inv + b4.x, acc[5]*inv + b4.y, acc[6]*inv + b4.z, acc[7]*inv + b4.w);
}

// ---------------- GEMM2 (relu on read) + attention logits layer 2 ----------------
__global__ void gemm2_kernel(const float* __restrict__ W2,
                             const float* __restrict__ att_src2,
                             const float* __restrict__ att_dst2) {
    __shared__ float w2s[F1 * 17];
    __shared__ float as2[OUT_C], ad2[OUT_C];
    int tid = threadIdx.x;
    for (int i = tid; i < F1 * OUT_C; i += 256) {
        int k = i >> 4, j = i & 15;
        w2s[k * 17 + j] = W2[i];
    }
    if (tid < OUT_C) { as2[tid] = att_src2[tid]; ad2[tid] = att_dst2[tid]; }
    __syncthreads();

    int gw   = (blockIdx.x * blockDim.x + tid) >> 5;
    int lane = tid & 31;
    if (gw >= NN) return;
    float acc[OUT_C] = {};
    const float* row = &g_out1[gw * F1];
    #pragma unroll
    for (int i = 0; i < 8; i++) {
        float v = fmaxf(row[lane + 32 * i], 0.f);
        const float* wr = &w2s[(lane + 32 * i) * 17];
        #pragma unroll
        for (int j = 0; j < OUT_C; j++) acc[j] = fmaf(v, wr[j], acc[j]);
    }
    #pragma unroll
    for (int j = 0; j < OUT_C; j++)
        #pragma unroll
        for (int o = 16; o; o >>= 1)
            acc[j] += __shfl_xor_sync(0xFFFFFFFFu, acc[j], o);
    if (lane == 0) {
        float s = 0.f, dd = 0.f;
        #pragma unroll
        for (int j = 0; j < OUT_C; j++) {
            g_h2[gw * OUT_C + j] = acc[j];
            s  += acc[j] * as2[j];
            dd += acc[j] * ad2[j];
        }
        g_asrc2[gw] = s; g_adst2[gw] = dd;
    }
}

// ---------------- fused layer-2 softmax + aggregation (one warp per dst node) ----------------
__global__ void agg2_kernel(const float* __restrict__ b2, float* __restrict__ out) {
    int gw   = (blockIdx.x * blockDim.x + threadIdx.x) >> 5;
    int lane = threadIdx.x & 31;
    if (gw >= NN) return;
    int n = gw;
    int beg = g_off[n], end = g_off[n+1];
    float ad = g_adst2[n];

    // pass 1: max (lane-strided)
    float m = -1e30f;
    for (int e = beg + lane; e < end; e += 32)
        m = fmaxf(m, leaky(g_asrc2[g_srcs[e]] + ad));
    #pragma unroll
    for (int o = 16; o; o >>= 1)
        m = fmaxf(m, __shfl_xor_sync(0xFFFFFFFFu, m, o));

    // pass 2: serial, accumulate (lane < 16 holds one output column)
    float den = 0.f, acc = 0.f;
    for (int e = beg; e < end; e++) {
        int s = g_srcs[e];
        float ex = __expf(leaky(g_asrc2[s] + ad) - m);
        den += ex;
        if (lane < OUT_C) acc = fmaf(ex, g_h2[s * OUT_C + lane], acc);
    }
    if (lane < OUT_C)
        out[n * OUT_C + lane] = acc / den + b2[lane];
}

// ---------------- launch ----------------
extern "C" void kernel_launch(void* const* d_in, const int* in_sizes, int n_in,
                              void* d_out, int out_size) {
    const float* x    = (const float*)d_in[0];
    const int*   ei   = (const int*)  d_in[1];
    const float* W1   = (const float*)d_in[2];
    const float* as1  = (const float*)d_in[3];
    const float* ad1  = (const float*)d_in[4];
    const float* b1   = (const float*)d_in[5];
    const float* W2   = (const float*)d_in[6];
    const float* as2  = (const float*)d_in[7];
    const float* ad2  = (const float*)d_in[8];
    const float* b2   = (const float*)d_in[9];
    float* out = (float*)d_out;

    // CSR build (grouped by dst)
    csr_init_kernel<<<(NN + 255) / 256, 256>>>();
    csr_hist_kernel<<<(ET + 255) / 256, 256>>>(ei);
    csr_scan_kernel<<<1, 1024>>>();
    csr_scatter_kernel<<<(ET + 255) / 256, 256>>>(ei);

    // layer 1
    gemm1_kernel<<<dim3(F1 / BN, (NN + BM - 1) / BM), 256>>>(x, W1);
    attn1_kernel<<<(NN*HEADS*32 + 255) / 256, 256>>>(as1, ad1);
    agg1_kernel<<<(NN*32 + 255) / 256, 256>>>(b1);

    // layer 2
    gemm2_kernel<<<(NN*32 + 255) / 256, 256>>>(W2, as2, ad2);
    agg2_kernel<<<(NN*32 + 255) / 256, 256>>>(b2, out);
}

// round 3
// speedup vs baseline: 1.5561x; 1.0749x over previous
#include <cuda_runtime.h>
#include <cuda_bf16.h>

// Problem constants (fixed by the dataset)
#define NN      50000
#define IN_C    128
#define HID     64
#define HEADS   4
#define OUT_C   16
#define EE      600000
#define ET      650000          // edges + self loops
#define F1      (HEADS*HID)     // 256
#define NEG_SLOPE 0.2f

// ---------------- scratch (static device globals; no allocation) ----------------
__device__ __align__(16) float g_h1[NN*F1];     // x @ W1            [N,256]
__device__ __align__(16) float g_out1[NN*F1];   // layer1 aggregated [N,256]
__device__ __align__(16) float g_h2[NN*OUT_C];  // relu(out1) @ W2   [N,16]
__device__ __align__(16) float g_asrc1[NN*HEADS];
__device__ __align__(16) float g_adst1[NN*HEADS];
__device__ float g_asrc2[NN], g_adst2[NN];
// CSR (grouped by dst)
__device__ int g_deg[NN];
__device__ int g_pos[NN];
__device__ int g_off[NN+1];
__device__ int g_srcs[ET];

// ---------------- helpers ----------------
__device__ __forceinline__ float leaky(float v) {
    return fmaxf(v, 0.f) + NEG_SLOPE * fminf(v, 0.f);
}

// ---------------- CSR build ----------------
__global__ void csr_init_kernel() {
    int t = blockIdx.x * blockDim.x + threadIdx.x;
    if (t < NN) { g_deg[t] = 1; g_pos[t] = 0; }   // deg=1 accounts for self loop
}
__global__ void csr_hist_kernel(const int* __restrict__ ei) {
    int eid = blockIdx.x * blockDim.x + threadIdx.x;
    if (eid >= EE) return;
    atomicAdd(&g_deg[ei[EE + eid]], 1);
}
__global__ void csr_scan_kernel() {   // single block, 1024 threads
    __shared__ int sh[1024];
    int t = threadIdx.x;
    const int CH = (NN + 1023) / 1024;
    int base = t * CH;
    int s = 0;
    for (int i = 0; i < CH; i++) { int id = base + i; if (id < NN) s += g_deg[id]; }
    sh[t] = s;
    __syncthreads();
    for (int off = 1; off < 1024; off <<= 1) {
        int v = (t >= off) ? sh[t - off] : 0;
        __syncthreads();
        sh[t] += v;
        __syncthreads();
    }
    int run = sh[t] - s;   // exclusive prefix
    for (int i = 0; i < CH; i++) {
        int id = base + i;
        if (id < NN) { g_off[id] = run; run += g_deg[id]; }
    }
    if (t == 1023) g_off[NN] = sh[1023];
}
__global__ void csr_scatter_kernel(const int* __restrict__ ei) {
    int eid = blockIdx.x * blockDim.x + threadIdx.x;
    if (eid >= ET) return;
    int s, d;
    if (eid < EE) { s = ei[eid]; d = ei[EE + eid]; }
    else          { s = d = eid - EE; }
    int p = atomicAdd(&g_pos[d], 1);
    g_srcs[g_off[d] + p] = s;
}

// ---------------- GEMM1: h1 = x @ W1 + fused attention logits ----------------
// 128x128 block tile, 8x8 per thread, BK=16
#define BM 128
#define BN 128
#define BK 16
__global__ void __launch_bounds__(256)
gemm1_kernel(const float* __restrict__ x, const float* __restrict__ W,
             const float* __restrict__ att_src, const float* __restrict__ att_dst) {
    __shared__ float xs[BK][BM + 4];
    __shared__ float ws[BK][BN + 4];
    int tid  = threadIdx.x;
    int row0 = blockIdx.y * BM;
    int col0 = blockIdx.x * BN;
    int ty = tid >> 4, tx = tid & 15;
    float acc[8][8] = {};

    for (int k0 = 0; k0 < IN_C; k0 += BK) {
        // x tile [BM][BK] -> transposed into xs[k][m]
        #pragma unroll
        for (int i = tid; i < BM * (BK/4); i += 256) {
            int r = i / (BK/4), c = (i % (BK/4)) * 4;
            int gr = row0 + r;
            float4 v = make_float4(0.f,0.f,0.f,0.f);
            if (gr < NN) v = *reinterpret_cast<const float4*>(&x[gr * IN_C + k0 + c]);
            xs[c][r] = v.x; xs[c+1][r] = v.y; xs[c+2][r] = v.z; xs[c+3][r] = v.w;
        }
        // W tile [BK][BN]
        #pragma unroll
        for (int i = tid; i < BK * (BN/4); i += 256) {
            int r = i / (BN/4), c = (i % (BN/4)) * 4;
            float4 v = *reinterpret_cast<const float4*>(&W[(k0 + r) * F1 + col0 + c]);
            ws[r][c] = v.x; ws[r][c+1] = v.y; ws[r][c+2] = v.z; ws[r][c+3] = v.w;
        }
        __syncthreads();
        #pragma unroll
        for (int k = 0; k < BK; k++) {
            float a[8], b[8];
            #pragma unroll
            for (int i = 0; i < 8; i++) a[i] = xs[k][ty*8 + i];
            #pragma unroll
            for (int j = 0; j < 8; j++) b[j] = ws[k][tx*8 + j];
            #pragma unroll
            for (int i = 0; i < 8; i++)
                #pragma unroll
                for (int j = 0; j < 8; j++)
                    acc[i][j] = fmaf(a[i], b[j], acc[i][j]);
        }
        __syncthreads();
    }

    // write h1
    #pragma unroll
    for (int i = 0; i < 8; i++) {
        int gr = row0 + ty*8 + i;
        if (gr < NN) {
            float4* op = reinterpret_cast<float4*>(&g_h1[gr * F1 + col0 + tx*8]);
            op[0] = make_float4(acc[i][0], acc[i][1], acc[i][2], acc[i][3]);
            op[1] = make_float4(acc[i][4], acc[i][5], acc[i][6], acc[i][7]);
        }
    }

    // fused attention-logit epilogue: this block covers 2 complete heads
    // head = col0/64 + tx/8; its 64 columns live in the 8 threads tx&~7 .. +7
    int head = (col0 >> 6) + (tx >> 3);
    const float4* asp = reinterpret_cast<const float4*>(&att_src[head * HID + (tx & 7) * 8]);
    const float4* adp = reinterpret_cast<const float4*>(&att_dst[head * HID + (tx & 7) * 8]);
    float4 s0 = asp[0], s1 = asp[1];
    float4 d0 = adp[0], d1 = adp[1];
    #pragma unroll
    for (int i = 0; i < 8; i++) {
        float sd = acc[i][0]*s0.x + acc[i][1]*s0.y + acc[i][2]*s0.z + acc[i][3]*s0.w
                 + acc[i][4]*s1.x + acc[i][5]*s1.y + acc[i][6]*s1.z + acc[i][7]*s1.w;
        float dd = acc[i][0]*d0.x + acc[i][1]*d0.y + acc[i][2]*d0.z + acc[i][3]*d0.w
                 + acc[i][4]*d1.x + acc[i][5]*d1.y + acc[i][6]*d1.z + acc[i][7]*d1.w;
        #pragma unroll
        for (int o = 1; o < 8; o <<= 1) {
            sd += __shfl_xor_sync(0xFFFFFFFFu, sd, o);
            dd += __shfl_xor_sync(0xFFFFFFFFu, dd, o);
        }
        int gr = row0 + ty*8 + i;
        if ((tx & 7) == 0 && gr < NN) {
            g_asrc1[gr * HEADS + head] = sd;
            g_adst1[gr * HEADS + head] = dd;
        }
    }
}

// ---------------- fused layer-1 softmax + aggregation (one warp per dst node) ----------------
__global__ void __launch_bounds__(256)
agg1_kernel(const float* __restrict__ b1) {
    int gw   = (blockIdx.x * blockDim.x + threadIdx.x) >> 5;
    int lane = threadIdx.x & 31;
    if (gw >= NN) return;
    int n = gw;
    int beg = g_off[n], end = g_off[n+1];
    float4 ad4 = *reinterpret_cast<const float4*>(&g_adst1[n * HEADS]);

    // pass 1: per-head max over incoming edges (lane-strided)
    float m0 = -1e30f, m1 = -1e30f, m2 = -1e30f, m3 = -1e30f;
    for (int e = beg + lane; e < end; e += 32) {
        int s = g_srcs[e];
        float4 as4 = *reinterpret_cast<const float4*>(&g_asrc1[s * HEADS]);
        m0 = fmaxf(m0, leaky(as4.x + ad4.x));
        m1 = fmaxf(m1, leaky(as4.y + ad4.y));
        m2 = fmaxf(m2, leaky(as4.z + ad4.z));
        m3 = fmaxf(m3, leaky(as4.w + ad4.w));
    }
    #pragma unroll
    for (int o = 16; o; o >>= 1) {
        m0 = fmaxf(m0, __shfl_xor_sync(0xFFFFFFFFu, m0, o));
        m1 = fmaxf(m1, __shfl_xor_sync(0xFFFFFFFFu, m1, o));
        m2 = fmaxf(m2, __shfl_xor_sync(0xFFFFFFFFu, m2, o));
        m3 = fmaxf(m3, __shfl_xor_sync(0xFFFFFFFFu, m3, o));
    }

    int hh = lane >> 3;                               // lane handles cols [lane*8, lane*8+8)
    float mh  = (hh == 0) ? m0 : (hh == 1) ? m1 : (hh == 2) ? m2 : m3;
    float adh = (hh == 0) ? ad4.x : (hh == 1) ? ad4.y : (hh == 2) ? ad4.z : ad4.w;

    // pass 2: unroll-2 software-pipelined gather + accumulate
    float den = 0.f;
    float acc[8] = {};
    int e = beg;
    for (; e + 1 < end; e += 2) {
        int sA = g_srcs[e], sB = g_srcs[e + 1];
        float asA = g_asrc1[sA * HEADS + hh];
        float asB = g_asrc1[sB * HEADS + hh];
        const float4* hA = reinterpret_cast<const float4*>(&g_h1[sA * F1 + lane * 8]);
        const float4* hB = reinterpret_cast<const float4*>(&g_h1[sB * F1 + lane * 8]);
        float4 a0 = hA[0], a1 = hA[1];
        float4 c0 = hB[0], c1 = hB[1];
        float exA = __expf(leaky(asA + adh) - mh);
        float exB = __expf(leaky(asB + adh) - mh);
        den += exA + exB;
        acc[0] = fmaf(exA, a0.x, fmaf(exB, c0.x, acc[0]));
        acc[1] = fmaf(exA, a0.y, fmaf(exB, c0.y, acc[1]));
        acc[2] = fmaf(exA, a0.z, fmaf(exB, c0.z, acc[2]));
        acc[3] = fmaf(exA, a0.w, fmaf(exB, c0.w, acc[3]));
        acc[4] = fmaf(exA, a1.x, fmaf(exB, c1.x, acc[4]));
        acc[5] = fmaf(exA, a1.y, fmaf(exB, c1.y, acc[5]));
        acc[6] = fmaf(exA, a1.z, fmaf(exB, c1.z, acc[6]));
        acc[7] = fmaf(exA, a1.w, fmaf(exB, c1.w, acc[7]));
    }
    if (e < end) {
        int s = g_srcs[e];
        float as = g_asrc1[s * HEADS + hh];
        const float4* hp = reinterpret_cast<const float4*>(&g_h1[s * F1 + lane * 8]);
        float4 v0 = hp[0], v1 = hp[1];
        float ex = __expf(leaky(as + adh) - mh);
        den += ex;
        acc[0] = fmaf(ex, v0.x, acc[0]); acc[1] = fmaf(ex, v0.y, acc[1]);
        acc[2] = fmaf(ex, v0.z, acc[2]); acc[3] = fmaf(ex, v0.w, acc[3]);
        acc[4] = fmaf(ex, v1.x, acc[4]); acc[5] = fmaf(ex, v1.y, acc[5]);
        acc[6] = fmaf(ex, v1.z, acc[6]); acc[7] = fmaf(ex, v1.w, acc[7]);
    }
    float inv = 1.f / den;
    float4 b0 = *reinterpret_cast<const float4*>(&b1[lane * 8]);
    float4 b4 = *reinterpret_cast<const float4*>(&b1[lane * 8 + 4]);
    float4* op = reinterpret_cast<float4*>(&g_out1[n * F1 + lane * 8]);
    op[0] = make_float4(acc[0]*inv + b0.x, acc[1]*inv + b0.y, acc[2]*inv + b0.z, acc[3]*inv + b0.w);
    op[1] = make_float4(acc[4]*inv + b4.x, acc[5]*inv + b4.y, acc[6]*inv + b4.z, acc[7]*inv + b4.w);
}

// ---------------- GEMM2 (relu on read) + attention logits layer 2 ----------------
__global__ void __launch_bounds__(256)
gemm2_kernel(const float* __restrict__ W2,
             const float* __restrict__ att_src2,
             const float* __restrict__ att_dst2) {
    __shared__ float w2s[F1 * 17];
    __shared__ float as2[OUT_C], ad2[OUT_C];
    int tid = threadIdx.x;
    for (int i = tid; i < F1 * OUT_C; i += 256) {
        int k = i >> 4, j = i & 15;
        w2s[k * 17 + j] = W2[i];
    }
    if (tid < OUT_C) { as2[tid] = att_src2[tid]; ad2[tid] = att_dst2[tid]; }
    __syncthreads();

    int gw   = (blockIdx.x * blockDim.x + tid) >> 5;
    int lane = tid & 31;
    if (gw >= NN) return;
    float acc[OUT_C] = {};
    const float* row = &g_out1[gw * F1];
    #pragma unroll
    for (int i = 0; i < 8; i++) {
        float v = fmaxf(row[lane + 32 * i], 0.f);
        const float* wr = &w2s[(lane + 32 * i) * 17];
        #pragma unroll
        for (int j = 0; j < OUT_C; j++) acc[j] = fmaf(v, wr[j], acc[j]);
    }
    #pragma unroll
    for (int j = 0; j < OUT_C; j++)
        #pragma unroll
        for (int o = 16; o; o >>= 1)
            acc[j] += __shfl_xor_sync(0xFFFFFFFFu, acc[j], o);
    if (lane == 0) {
        float s = 0.f, dd = 0.f;
        #pragma unroll
        for (int j = 0; j < OUT_C; j++) {
            g_h2[gw * OUT_C + j] = acc[j];
            s  += acc[j] * as2[j];
            dd += acc[j] * ad2[j];
        }
        g_asrc2[gw] = s; g_adst2[gw] = dd;
    }
}

// ---------------- fused layer-2 softmax + aggregation (one warp per dst node) ----------------
__global__ void __launch_bounds__(256)
agg2_kernel(const float* __restrict__ b2, float* __restrict__ out) {
    int gw   = (blockIdx.x * blockDim.x + threadIdx.x) >> 5;
    int lane = threadIdx.x & 31;
    if (gw >= NN) return;
    int n = gw;
    int beg = g_off[n], end = g_off[n+1];
    float ad = g_adst2[n];

    // pass 1: max (lane-strided)
    float m = -1e30f;
    for (int e = beg + lane; e < end; e += 32)
        m = fmaxf(m, leaky(g_asrc2[g_srcs[e]] + ad));
    #pragma unroll
    for (int o = 16; o; o >>= 1)
        m = fmaxf(m, __shfl_xor_sync(0xFFFFFFFFu, m, o));

    // pass 2: unroll-2 accumulate (lane < 16 holds one output column)
    float den = 0.f, acc = 0.f;
    int e = beg;
    for (; e + 1 < end; e += 2) {
        int sA = g_srcs[e], sB = g_srcs[e + 1];
        float exA = __expf(leaky(g_asrc2[sA] + ad) - m);
        float exB = __expf(leaky(g_asrc2[sB] + ad) - m);
        float hA = (lane < OUT_C) ? g_h2[sA * OUT_C + lane] : 0.f;
        float hB = (lane < OUT_C) ? g_h2[sB * OUT_C + lane] : 0.f;
        den += exA + exB;
        acc = fmaf(exA, hA, fmaf(exB, hB, acc));
    }
    if (e < end) {
        int s = g_srcs[e];
        float ex = __expf(leaky(g_asrc2[s] + ad) - m);
        den += ex;
        if (lane < OUT_C) acc = fmaf(ex, g_h2[s * OUT_C + lane], acc);
    }
    if (lane < OUT_C)
        out[n * OUT_C + lane] = acc / den + b2[lane];
}

// ---------------- launch ----------------
extern "C" void kernel_launch(void* const* d_in, const int* in_sizes, int n_in,
                              void* d_out, int out_size) {
    const float* x    = (const float*)d_in[0];
    const int*   ei   = (const int*)  d_in[1];
    const float* W1   = (const float*)d_in[2];
    const float* as1  = (const float*)d_in[3];
    const float* ad1  = (const float*)d_in[4];
    const float* b1   = (const float*)d_in[5];
    const float* W2   = (const float*)d_in[6];
    const float* as2  = (const float*)d_in[7];
    const float* ad2  = (const float*)d_in[8];
    const float* b2   = (const float*)d_in[9];
    float* out = (float*)d_out;

    // CSR build (grouped by dst)
    csr_init_kernel<<<(NN + 255) / 256, 256>>>();
    csr_hist_kernel<<<(EE + 255) / 256, 256>>>(ei);
    csr_scan_kernel<<<1, 1024>>>();
    csr_scatter_kernel<<<(ET + 255) / 256, 256>>>(ei);

    // layer 1
    gemm1_kernel<<<dim3(F1 / BN, (NN + BM - 1) / BM), 256>>>(x, W1, as1, ad1);
    agg1_kernel<<<(NN*32 + 255) / 256, 256>>>(b1);

    // layer 2
    gemm2_kernel<<<(NN*32 + 255) / 256, 256>>>(W2, as2, ad2);
    agg2_kernel<<<(NN*32 + 255) / 256, 256>>>(b2, out);
}

// round 4
// speedup vs baseline: 1.7531x; 1.1266x over previous
#include <cuda_runtime.h>
#include <cuda_fp16.h>

// Problem constants (fixed by the dataset)
#define NN      50000
#define IN_C    128
#define HID     64
#define HEADS   4
#define OUT_C   16
#define EE      600000
#define ET      650000          // edges + self loops
#define F1      (HEADS*HID)     // 256
#define NEG_SLOPE 0.2f

// ---------------- scratch (static device globals; no allocation) ----------------
__device__ __align__(16) __half g_h1h[NN*F1];   // x @ W1 (fp16 gather table) [N,256]
__device__ __align__(16) float  g_out1[NN*F1];  // layer1 aggregated          [N,256]
__device__ __align__(16) float  g_h2[NN*OUT_C]; // relu(out1) @ W2            [N,16]
__device__ __align__(16) float  g_asrc1[NN*HEADS];
__device__ __align__(16) float  g_adst1[NN*HEADS];
__device__ float g_asrc2[NN], g_adst2[NN];
// CSR (grouped by dst)
__device__ int g_deg[NN];
__device__ int g_pos[NN];
__device__ int g_off[NN+1];
__device__ int g_srcs[ET];

// ---------------- helpers ----------------
__device__ __forceinline__ float leaky(float v) {
    return fmaxf(v, 0.f) + NEG_SLOPE * fminf(v, 0.f);
}

// ---------------- CSR build ----------------
__global__ void csr_init_kernel() {
    int t = blockIdx.x * blockDim.x + threadIdx.x;
    if (t < NN) { g_deg[t] = 1; g_pos[t] = 0; }   // deg=1 accounts for self loop
}
__global__ void csr_hist_kernel(const int* __restrict__ ei) {
    int eid = blockIdx.x * blockDim.x + threadIdx.x;
    if (eid >= EE) return;
    atomicAdd(&g_deg[ei[EE + eid]], 1);
}
__global__ void csr_scan_kernel() {   // single block, 1024 threads
    __shared__ int sh[1024];
    int t = threadIdx.x;
    const int CH = (NN + 1023) / 1024;
    int base = t * CH;
    int s = 0;
    for (int i = 0; i < CH; i++) { int id = base + i; if (id < NN) s += g_deg[id]; }
    sh[t] = s;
    __syncthreads();
    for (int off = 1; off < 1024; off <<= 1) {
        int v = (t >= off) ? sh[t - off] : 0;
        __syncthreads();
        sh[t] += v;
        __syncthreads();
    }
    int run = sh[t] - s;   // exclusive prefix
    for (int i = 0; i < CH; i++) {
        int id = base + i;
        if (id < NN) { g_off[id] = run; run += g_deg[id]; }
    }
    if (t == 1023) g_off[NN] = sh[1023];
}
__global__ void csr_scatter_kernel(const int* __restrict__ ei) {
    int eid = blockIdx.x * blockDim.x + threadIdx.x;
    if (eid >= ET) return;
    int s, d;
    if (eid < EE) { s = ei[eid]; d = ei[EE + eid]; }
    else          { s = d = eid - EE; }
    int p = atomicAdd(&g_pos[d], 1);
    g_srcs[g_off[d] + p] = s;
}

// ---------------- GEMM1: h1 = x @ W1 (fp16 out) + fused attention logits ----------------
// 128x128 block tile, 8x8 per thread, BK=16, register-staged double buffering
#define BM 128
#define BN 128
#define BK 16
__global__ void __launch_bounds__(256)
gemm1_kernel(const float* __restrict__ x, const float* __restrict__ W,
             const float* __restrict__ att_src, const float* __restrict__ att_dst) {
    __shared__ float xs[2][BK][BM + 4];
    __shared__ float ws[2][BK][BN + 4];
    int tid  = threadIdx.x;
    int row0 = blockIdx.y * BM;
    int col0 = blockIdx.x * BN;
    int ty = tid >> 4, tx = tid & 15;
    float acc[8][8] = {};

    // per-thread load coordinates
    int xr_r0 = (tid >> 2),  xr_c = (tid & 3) * 4;    // x tile: rows xr_r0, xr_r0+64
    int wr_r0 = (tid >> 5),  wr_c = (tid & 31) * 4;   // W tile: rows wr_r0, wr_r0+8

    float4 xr[2], wr[2];
    auto ldg_tiles = [&](int k0) {
        #pragma unroll
        for (int j = 0; j < 2; j++) {
            int gr = row0 + xr_r0 + j * 64;
            xr[j] = (gr < NN) ? *reinterpret_cast<const float4*>(&x[gr * IN_C + k0 + xr_c])
                              : make_float4(0.f, 0.f, 0.f, 0.f);
            wr[j] = *reinterpret_cast<const float4*>(&W[(k0 + wr_r0 + j * 8) * F1 + col0 + wr_c]);
        }
    };
    auto sts_tiles = [&](int b) {
        #pragma unroll
        for (int j = 0; j < 2; j++) {
            int r = xr_r0 + j * 64;
            xs[b][xr_c  ][r] = xr[j].x; xs[b][xr_c+1][r] = xr[j].y;
            xs[b][xr_c+2][r] = xr[j].z; xs[b][xr_c+3][r] = xr[j].w;
            int rw = wr_r0 + j * 8;
            ws[b][rw][wr_c  ] = wr[j].x; ws[b][rw][wr_c+1] = wr[j].y;
            ws[b][rw][wr_c+2] = wr[j].z; ws[b][rw][wr_c+3] = wr[j].w;
        }
    };

    ldg_tiles(0);
    sts_tiles(0);
    __syncthreads();

    const int NK = IN_C / BK;   // 8
    for (int k0 = 0; k0 < NK; k0++) {
        int b = k0 & 1;
        if (k0 + 1 < NK) ldg_tiles((k0 + 1) * BK);
        #pragma unroll
        for (int k = 0; k < BK; k++) {
            float a[8], c[8];
            #pragma unroll
            for (int i = 0; i < 8; i++) a[i] = xs[b][k][ty*8 + i];
            #pragma unroll
            for (int j = 0; j < 8; j++) c[j] = ws[b][k][tx*8 + j];
            #pragma unroll
            for (int i = 0; i < 8; i++)
                #pragma unroll
                for (int j = 0; j < 8; j++)
                    acc[i][j] = fmaf(a[i], c[j], acc[i][j]);
        }
        if (k0 + 1 < NK) sts_tiles(b ^ 1);
        __syncthreads();
    }

    // write h1 as fp16 (8 halves = 16B per row slice)
    #pragma unroll
    for (int i = 0; i < 8; i++) {
        int gr = row0 + ty*8 + i;
        if (gr < NN) {
            __half2 h[4];
            h[0] = __floats2half2_rn(acc[i][0], acc[i][1]);
            h[1] = __floats2half2_rn(acc[i][2], acc[i][3]);
            h[2] = __floats2half2_rn(acc[i][4], acc[i][5]);
            h[3] = __floats2half2_rn(acc[i][6], acc[i][7]);
            *reinterpret_cast<uint4*>(&g_h1h[gr * F1 + col0 + tx*8]) =
                *reinterpret_cast<const uint4*>(h);
        }
    }

    // fused attention-logit epilogue (fp32, from accumulators)
    int head = (col0 >> 6) + (tx >> 3);
    const float4* asp = reinterpret_cast<const float4*>(&att_src[head * HID + (tx & 7) * 8]);
    const float4* adp = reinterpret_cast<const float4*>(&att_dst[head * HID + (tx & 7) * 8]);
    float4 s0 = asp[0], s1 = asp[1];
    float4 d0 = adp[0], d1 = adp[1];
    #pragma unroll
    for (int i = 0; i < 8; i++) {
        float sd = acc[i][0]*s0.x + acc[i][1]*s0.y + acc[i][2]*s0.z + acc[i][3]*s0.w
                 + acc[i][4]*s1.x + acc[i][5]*s1.y + acc[i][6]*s1.z + acc[i][7]*s1.w;
        float dd = acc[i][0]*d0.x + acc[i][1]*d0.y + acc[i][2]*d0.z + acc[i][3]*d0.w
                 + acc[i][4]*d1.x + acc[i][5]*d1.y + acc[i][6]*d1.z + acc[i][7]*d1.w;
        #pragma unroll
        for (int o = 1; o < 8; o <<= 1) {
            sd += __shfl_xor_sync(0xFFFFFFFFu, sd, o);
            dd += __shfl_xor_sync(0xFFFFFFFFu, dd, o);
        }
        int gr = row0 + ty*8 + i;
        if ((tx & 7) == 0 && gr < NN) {
            g_asrc1[gr * HEADS + head] = sd;
            g_adst1[gr * HEADS + head] = dd;
        }
    }
}

// ---------------- fused layer-1 softmax + aggregation (one warp per dst node) ----------------
__device__ __forceinline__ void acc_row(float acc[8], float ex, uint4 r) {
    const __half2* p = reinterpret_cast<const __half2*>(&r);
    #pragma unroll
    for (int j = 0; j < 4; j++) {
        float2 f = __half22float2(p[j]);
        acc[2*j]   = fmaf(ex, f.x, acc[2*j]);
        acc[2*j+1] = fmaf(ex, f.y, acc[2*j+1]);
    }
}
__global__ void __launch_bounds__(256)
agg1_kernel(const float* __restrict__ b1) {
    int gw   = (blockIdx.x * blockDim.x + threadIdx.x) >> 5;
    int lane = threadIdx.x & 31;
    if (gw >= NN) return;
    int n = gw;
    int beg = g_off[n], end = g_off[n+1];
    float4 ad4 = *reinterpret_cast<const float4*>(&g_adst1[n * HEADS]);

    // pass 1: per-head max over incoming edges (lane-strided)
    float m0 = -1e30f, m1 = -1e30f, m2 = -1e30f, m3 = -1e30f;
    for (int e = beg + lane; e < end; e += 32) {
        int s = g_srcs[e];
        float4 as4 = *reinterpret_cast<const float4*>(&g_asrc1[s * HEADS]);
        m0 = fmaxf(m0, leaky(as4.x + ad4.x));
        m1 = fmaxf(m1, leaky(as4.y + ad4.y));
        m2 = fmaxf(m2, leaky(as4.z + ad4.z));
        m3 = fmaxf(m3, leaky(as4.w + ad4.w));
    }
    #pragma unroll
    for (int o = 16; o; o >>= 1) {
        m0 = fmaxf(m0, __shfl_xor_sync(0xFFFFFFFFu, m0, o));
        m1 = fmaxf(m1, __shfl_xor_sync(0xFFFFFFFFu, m1, o));
        m2 = fmaxf(m2, __shfl_xor_sync(0xFFFFFFFFu, m2, o));
        m3 = fmaxf(m3, __shfl_xor_sync(0xFFFFFFFFu, m3, o));
    }

    int hh = lane >> 3;                               // lane handles cols [lane*8, lane*8+8)
    float mh  = (hh == 0) ? m0 : (hh == 1) ? m1 : (hh == 2) ? m2 : m3;
    float adh = (hh == 0) ? ad4.x : (hh == 1) ? ad4.y : (hh == 2) ? ad4.z : ad4.w;

    // pass 2: unroll-4 gather (1 LDG.128/lane/edge, MLP=4) + fp32 accumulate
    float den = 0.f;
    float acc[8] = {};
    int e = beg;
    for (; e + 3 < end; e += 4) {
        int s0 = g_srcs[e], s1 = g_srcs[e+1], s2 = g_srcs[e+2], s3 = g_srcs[e+3];
        uint4 r0 = *reinterpret_cast<const uint4*>(&g_h1h[s0 * F1 + lane * 8]);
        uint4 r1 = *reinterpret_cast<const uint4*>(&g_h1h[s1 * F1 + lane * 8]);
        uint4 r2 = *reinterpret_cast<const uint4*>(&g_h1h[s2 * F1 + lane * 8]);
        uint4 r3 = *reinterpret_cast<const uint4*>(&g_h1h[s3 * F1 + lane * 8]);
        float ex0 = __expf(leaky(g_asrc1[s0 * HEADS + hh] + adh) - mh);
        float ex1 = __expf(leaky(g_asrc1[s1 * HEADS + hh] + adh) - mh);
        float ex2 = __expf(leaky(g_asrc1[s2 * HEADS + hh] + adh) - mh);
        float ex3 = __expf(leaky(g_asrc1[s3 * HEADS + hh] + adh) - mh);
        den += (ex0 + ex1) + (ex2 + ex3);
        acc_row(acc, ex0, r0);
        acc_row(acc, ex1, r1);
        acc_row(acc, ex2, r2);
        acc_row(acc, ex3, r3);
    }
    for (; e < end; e++) {
        int s = g_srcs[e];
        uint4 r = *reinterpret_cast<const uint4*>(&g_h1h[s * F1 + lane * 8]);
        float ex = __expf(leaky(g_asrc1[s * HEADS + hh] + adh) - mh);
        den += ex;
        acc_row(acc, ex, r);
    }
    float inv = 1.f / den;
    float4 b0 = *reinterpret_cast<const float4*>(&b1[lane * 8]);
    float4 b4 = *reinterpret_cast<const float4*>(&b1[lane * 8 + 4]);
    float4* op = reinterpret_cast<float4*>(&g_out1[n * F1 + lane * 8]);
    op[0] = make_float4(acc[0]*inv + b0.x, acc[1]*inv + b0.y, acc[2]*inv + b0.z, acc[3]*inv + b0.w);
    op[1] = make_float4(acc[4]*inv + b4.x, acc[5]*inv + b4.y, acc[6]*inv + b4.z, acc[7]*inv + b4.w);
}

// ---------------- GEMM2 (relu on read) + attention logits layer 2 ----------------
__global__ void __launch_bounds__(256)
gemm2_kernel(const float* __restrict__ W2,
             const float* __restrict__ att_src2,
             const float* __restrict__ att_dst2) {
    __shared__ float w2s[F1 * 17];
    __shared__ float as2[OUT_C], ad2[OUT_C];
    int tid = threadIdx.x;
    for (int i = tid; i < F1 * OUT_C; i += 256) {
        int k = i >> 4, j = i & 15;
        w2s[k * 17 + j] = W2[i];
    }
    if (tid < OUT_C) { as2[tid] = att_src2[tid]; ad2[tid] = att_dst2[tid]; }
    __syncthreads();

    int gw   = (blockIdx.x * blockDim.x + tid) >> 5;
    int lane = tid & 31;
    if (gw >= NN) return;
    float acc[OUT_C] = {};
    const float* row = &g_out1[gw * F1];
    #pragma unroll
    for (int i = 0; i < 8; i++) {
        float v = fmaxf(row[lane + 32 * i], 0.f);
        const float* wrp = &w2s[(lane + 32 * i) * 17];
        #pragma unroll
        for (int j = 0; j < OUT_C; j++) acc[j] = fmaf(v, wrp[j], acc[j]);
    }
    #pragma unroll
    for (int j = 0; j < OUT_C; j++)
        #pragma unroll
        for (int o = 16; o; o >>= 1)
            acc[j] += __shfl_xor_sync(0xFFFFFFFFu, acc[j], o);
    if (lane == 0) {
        float s = 0.f, dd = 0.f;
        #pragma unroll
        for (int j = 0; j < OUT_C; j++) {
            g_h2[gw * OUT_C + j] = acc[j];
            s  += acc[j] * as2[j];
            dd += acc[j] * ad2[j];
        }
        g_asrc2[gw] = s; g_adst2[gw] = dd;
    }
}

// ---------------- fused layer-2 softmax + aggregation (one warp per dst node) ----------------
__global__ void __launch_bounds__(256)
agg2_kernel(const float* __restrict__ b2, float* __restrict__ out) {
    int gw   = (blockIdx.x * blockDim.x + threadIdx.x) >> 5;
    int lane = threadIdx.x & 31;
    if (gw >= NN) return;
    int n = gw;
    int beg = g_off[n], end = g_off[n+1];
    float ad = g_adst2[n];

    // pass 1: max (lane-strided)
    float m = -1e30f;
    for (int e = beg + lane; e < end; e += 32)
        m = fmaxf(m, leaky(g_asrc2[g_srcs[e]] + ad));
    #pragma unroll
    for (int o = 16; o; o >>= 1)
        m = fmaxf(m, __shfl_xor_sync(0xFFFFFFFFu, m, o));

    // pass 2: unroll-2 accumulate (lane < 16 holds one output column)
    float den = 0.f, acc = 0.f;
    int e = beg;
    for (; e + 1 < end; e += 2) {
        int sA = g_srcs[e], sB = g_srcs[e + 1];
        float exA = __expf(leaky(g_asrc2[sA] + ad) - m);
        float exB = __expf(leaky(g_asrc2[sB] + ad) - m);
        float hA = (lane < OUT_C) ? g_h2[sA * OUT_C + lane] : 0.f;
        float hB = (lane < OUT_C) ? g_h2[sB * OUT_C + lane] : 0.f;
        den += exA + exB;
        acc = fmaf(exA, hA, fmaf(exB, hB, acc));
    }
    if (e < end) {
        int s = g_srcs[e];
        float ex = __expf(leaky(g_asrc2[s] + ad) - m);
        den += ex;
        if (lane < OUT_C) acc = fmaf(ex, g_h2[s * OUT_C + lane], acc);
    }
    if (lane < OUT_C)
        out[n * OUT_C + lane] = acc / den + b2[lane];
}

// ---------------- launch ----------------
extern "C" void kernel_launch(void* const* d_in, const int* in_sizes, int n_in,
                              void* d_out, int out_size) {
    const float* x    = (const float*)d_in[0];
    const int*   ei   = (const int*)  d_in[1];
    const float* W1   = (const float*)d_in[2];
    const float* as1  = (const float*)d_in[3];
    const float* ad1  = (const float*)d_in[4];
    const float* b1   = (const float*)d_in[5];
    const float* W2   = (const float*)d_in[6];
    const float* as2  = (const float*)d_in[7];
    const float* ad2  = (const float*)d_in[8];
    const float* b2   = (const float*)d_in[9];
    float* out = (float*)d_out;

    // CSR build (grouped by dst)
    csr_init_kernel<<<(NN + 255) / 256, 256>>>();
    csr_hist_kernel<<<(EE + 255) / 256, 256>>>(ei);
    csr_scan_kernel<<<1, 1024>>>();
    csr_scatter_kernel<<<(ET + 255) / 256, 256>>>(ei);

    // layer 1
    gemm1_kernel<<<dim3(F1 / BN, (NN + BM - 1) / BM), 256>>>(x, W1, as1, ad1);
    agg1_kernel<<<(NN*32 + 255) / 256, 256>>>(b1);

    // layer 2
    gemm2_kernel<<<(NN*32 + 255) / 256, 256>>>(W2, as2, ad2);
    agg2_kernel<<<(NN*32 + 255) / 256, 256>>>(b2, out);
}